// round 15
// baseline (speedup 1.0000x reference)
#include <cuda_runtime.h>
#include <cstdint>

// ============================================================================
// NegativeContrastiveLoss: x[8192,256] fp32 ->
//   xn = x / max(||x||_2, 1e-12)  (rows)
//   S  = xn @ xn^T / 0.1 ; E = exp(S) with diag zeroed
//   loss = mean_i log( sum_j E_ij / (N-1) + 1e-8 )
//
// R15: int8 IMMA (mma.sync m16n8k32 s8.s8.s32) — 2x K-depth per instruction
//      vs fp16 m16n8k16, attacking the measured ~12.5 cyc/instr legacy-MMA
//      issue ceiling by halving instruction count. Per-row symmetric int8
//      quantization, exact s32 accumulation, scales (x sqrt(1/tau*log2e))
//      applied in the epilogue. ldmatrix addressing is byte-identical to the
//      fp16 version (16B-granular rows), K bookkeeping doubled.
//      Keeps: symmetry (2080 upper-tri 128x128 tiles, row+col sums),
//      cp.async pipeline (2 chunks, both in flight), occupancy-2 mainloop.
// ============================================================================

#define NROWS 8192
#define DIM   256
#define SFAC  3.79828262f          // sqrt(14.4269504089)
#define EPS   1e-8f

__device__ __align__(256) signed char g_xq[NROWS * DIM];  // 2 MB, int8 rows
__device__ float g_scale[NROWS];                          // per-row scale * SFAC
__device__ float g_rowsum[NROWS];

static __device__ __forceinline__ unsigned smem_u32(const void* p) {
    unsigned a;
    asm("{ .reg .u64 t; cvta.to.shared.u64 t, %1; cvt.u32.u64 %0, t; }" : "=r"(a) : "l"(p));
    return a;
}
static __device__ __forceinline__ void cp_async16(unsigned saddr, const void* gptr) {
    asm volatile("cp.async.cg.shared.global [%0], [%1], 16;"
                 :: "r"(saddr), "l"(gptr) : "memory");
}
static __device__ __forceinline__ void ldmatrix_x4(unsigned& r0, unsigned& r1,
                                                   unsigned& r2, unsigned& r3,
                                                   unsigned addr) {
    asm volatile("ldmatrix.sync.aligned.m8n8.x4.shared.b16 {%0,%1,%2,%3}, [%4];"
                 : "=r"(r0), "=r"(r1), "=r"(r2), "=r"(r3) : "r"(addr));
}
// int8 MMA, K=32 per instruction, exact s32 accumulate
static __device__ __forceinline__ void mma_s8(int* c, const unsigned* a,
                                              const unsigned* b) {
    asm volatile(
        "mma.sync.aligned.m16n8k32.row.col.s32.s8.s8.s32 "
        "{%0,%1,%2,%3}, {%4,%5,%6,%7}, {%8,%9}, {%0,%1,%2,%3};"
        : "+r"(c[0]), "+r"(c[1]), "+r"(c[2]), "+r"(c[3])
        : "r"(a[0]), "r"(a[1]), "r"(a[2]), "r"(a[3]), "r"(b[0]), "r"(b[1]));
}
static __device__ __forceinline__ float ex2f(float v) {
    float e;
    asm("ex2.approx.f32 %0, %1;" : "=f"(e) : "f"(v));
    return e;
}

// ---------------------------------------------------------------------------
// Kernel 1: row L2-normalize + per-row int8 quantization.
// 2048 blocks x 256 threads; 64 threads/row; one float4 per thread.
// q = round(v * 127 / rowmax_v)   (inv_norm cancels in quantization)
// g_scale[row] = rowmax_v * inv_norm / 127 * SFAC
// ---------------------------------------------------------------------------
__global__ __launch_bounds__(256) void k_normalize(const float* __restrict__ x,
                                                   float* __restrict__ out) {
    __shared__ float ws[8], wm[8];
    int tid = threadIdx.x;
    if (tid < 4) g_rowsum[blockIdx.x * 4 + tid] = 0.0f;
    if (blockIdx.x == 0 && tid == 0) out[0] = 0.0f;

    int row = blockIdx.x * 4 + (tid >> 6);
    int t64 = tid & 63;
    float4 v = reinterpret_cast<const float4*>(x)[row * (DIM / 4) + t64];
    float s = v.x * v.x + v.y * v.y + v.z * v.z + v.w * v.w;
    float m = fmaxf(fmaxf(fabsf(v.x), fabsf(v.y)), fmaxf(fabsf(v.z), fabsf(v.w)));
#pragma unroll
    for (int o = 16; o; o >>= 1) {
        s += __shfl_xor_sync(0xFFFFFFFFu, s, o);
        m = fmaxf(m, __shfl_xor_sync(0xFFFFFFFFu, m, o));
    }
    if ((tid & 31) == 0) { ws[tid >> 5] = s; wm[tid >> 5] = m; }
    __syncthreads();
    int half = (tid >> 6) * 2;
    s = ws[half] + ws[half + 1];
    m = fmaxf(wm[half], wm[half + 1]);
    float inv = 1.0f / fmaxf(sqrtf(s), 1e-12f);
    float qs  = 127.0f / fmaxf(m, 1e-12f);

    int q0 = __float2int_rn(v.x * qs);
    int q1 = __float2int_rn(v.y * qs);
    int q2 = __float2int_rn(v.z * qs);
    int q3 = __float2int_rn(v.w * qs);
    unsigned p = (unsigned)(q0 & 0xFF) | ((unsigned)(q1 & 0xFF) << 8) |
                 ((unsigned)(q2 & 0xFF) << 16) | ((unsigned)q3 << 24);
    reinterpret_cast<unsigned*>(g_xq)[row * (DIM / 4) + t64] = p;

    if (t64 == 0) g_scale[row] = m * inv * (SFAC / 127.0f);
}

// ---------------------------------------------------------------------------
// Kernel 2: fused int8 GEMM + exp2 + row/col sums, upper-triangular tiles.
//
// CTA tile 128x128. K=256 s8 in 2 chunks of 128 bytes; both chunks' cp.async
// issued upfront (4 buffers, 64 KB total). Buffer: 128 rows x 128 B,
// 16B-granule XOR swizzle (ch ^ (r&7)). 8 warps as 4(M) x 2(N), warp 32x64.
// Mainloop: per chunk 4 k32-steps x 16 IMMA/warp -> 128 IMMA/warp total
// (half the fp16 instruction count). Epilogue: acc * srow * scol is directly
// the exp2 argument (scales carry sqrt(1/tau*log2e)).
// ---------------------------------------------------------------------------
#define CHUNK_BYTES 32768           // A(16K) + B(16K)
#define SMEM_TOT    65536
#define NB 64
#define NTILES (NB * (NB + 1) / 2)  // 2080

__global__ __launch_bounds__(256, 2) void k_gemm() {
    extern __shared__ char smem[];
    unsigned sb = smem_u32(smem);
    int tid  = threadIdx.x;
    int wid  = tid >> 5, lane = tid & 31;

    // triangular decode: k -> (bi, bj), bi <= bj
    int k = blockIdx.x;
    int bi = (int)floorf((float)NB + 0.5f -
                         sqrtf(((float)NB + 0.5f) * ((float)NB + 0.5f) - 2.0f * (float)k));
    while (NB * (bi + 1) - ((bi + 1) * bi) / 2 <= k) bi++;
    while (NB * bi - (bi * (bi - 1)) / 2 > k) bi--;
    int bj = bi + (k - (NB * bi - (bi * (bi - 1)) / 2));
    bool diag = (bi == bj);

    int warp_m = (wid & 3) * 32;
    int warp_n = (wid >> 2) * 64;

    // cp.async coords: 4 iters x 256 thr = 1024 x 16B per 128x128B buffer
    int lr = tid >> 3;                 // row base (0..31), +32/iter
    int lc = tid & 7;                  // 16B chunk in 128B row
    unsigned ssw = (unsigned)((lc ^ (lr & 7)) << 4);
    const char* gA = reinterpret_cast<const char*>(g_xq) + (size_t)(bi * 128 + lr) * 256 + lc * 16;
    const char* gB = reinterpret_cast<const char*>(g_xq) + (size_t)(bj * 128 + lr) * 256 + lc * 16;

#define ISSUE_CHUNK(kc)                                                          \
    do {                                                                         \
        unsigned ab_ = sb + (kc) * CHUNK_BYTES;                                  \
        unsigned bb_ = ab_ + 16384;                                              \
        _Pragma("unroll")                                                        \
        for (int it = 0; it < 4; it++)                                           \
            cp_async16(ab_ + (unsigned)(lr + it * 32) * 128 + ssw,               \
                       gA + (size_t)it * 32 * 256 + (kc) * 128);                 \
        _Pragma("unroll")                                                        \
        for (int it = 0; it < 4; it++)                                           \
            cp_async16(bb_ + (unsigned)(lr + it * 32) * 128 + ssw,               \
                       gB + (size_t)it * 32 * 256 + (kc) * 128);                 \
        asm volatile("cp.async.commit_group;" ::: "memory");                     \
    } while (0)

    int acc[2][8][4];
#pragma unroll
    for (int mf = 0; mf < 2; mf++)
#pragma unroll
        for (int nf = 0; nf < 8; nf++)
#pragma unroll
            for (int j = 0; j < 4; j++) acc[mf][nf][j] = 0;

    ISSUE_CHUNK(0);
    ISSUE_CHUNK(1);

#pragma unroll
    for (int kc = 0; kc < 2; kc++) {
        if (kc == 0) asm volatile("cp.async.wait_group 1;" ::: "memory");
        else         asm volatile("cp.async.wait_group 0;" ::: "memory");
        __syncthreads();

        unsigned ab = sb + kc * CHUNK_BYTES;
        unsigned bb = ab + 16384;

#pragma unroll
        for (int ks = 0; ks < 4; ks++) {           // k32 steps within 128B
            unsigned a[2][4];
#pragma unroll
            for (int mf = 0; mf < 2; mf++) {
                int r = warp_m + mf * 16 + (lane & 15);
                int ch = ks * 2 + (lane >> 4);
                ldmatrix_x4(a[mf][0], a[mf][1], a[mf][2], a[mf][3],
                            ab + r * 128 + ((ch ^ (r & 7)) << 4));
            }
            unsigned b[8][2];
#pragma unroll
            for (int p = 0; p < 4; p++) {
                int g = lane >> 3;
                int r = warp_n + p * 16 + (g >> 1) * 8 + (lane & 7);
                int ch = ks * 2 + (g & 1);
                unsigned r0, r1, r2, r3;
                ldmatrix_x4(r0, r1, r2, r3, bb + r * 128 + ((ch ^ (r & 7)) << 4));
                b[p * 2 + 0][0] = r0; b[p * 2 + 0][1] = r1;
                b[p * 2 + 1][0] = r2; b[p * 2 + 1][1] = r3;
            }
#pragma unroll
            for (int mf = 0; mf < 2; mf++)
#pragma unroll
                for (int nf = 0; nf < 8; nf++)
                    mma_s8(acc[mf][nf], a[mf], b[nf]);
        }
    }

    // ---- epilogue: scale -> exp2, diag zero, row sums + col sums ----
    __syncthreads();                 // done reading mainloop buffers
    float* colsum = reinterpret_cast<float*>(smem);          // 128 floats
    float* srow   = reinterpret_cast<float*>(smem + 512);    // 128 floats
    float* scol   = reinterpret_cast<float*>(smem + 1024);   // 128 floats
    if (tid < 128) {
        srow[tid] = g_scale[bi * 128 + tid];
        scol[tid] = g_scale[bj * 128 + tid];
        colsum[tid] = 0.0f;
    }
    __syncthreads();

    int lrow = lane >> 2;
    float rsc[4];
    rsc[0] = srow[warp_m + lrow];
    rsc[1] = srow[warp_m + 8 + lrow];
    rsc[2] = srow[warp_m + 16 + lrow];
    rsc[3] = srow[warp_m + 24 + lrow];

    float rs[4] = {0.0f, 0.0f, 0.0f, 0.0f};
#pragma unroll
    for (int nf = 0; nf < 8; nf++) {
        float c0 = 0.0f, c1 = 0.0f;
        int coll = warp_n + nf * 8 + (lane & 3) * 2;
        int gcol0 = bj * 128 + coll;
        float cs0 = scol[coll], cs1 = scol[coll + 1];
#pragma unroll
        for (int mf = 0; mf < 2; mf++) {
            int grow0 = bi * 128 + warp_m + mf * 16 + lrow;
            float f00 = rsc[mf * 2 + 0] * cs0, f01 = rsc[mf * 2 + 0] * cs1;
            float f10 = rsc[mf * 2 + 1] * cs0, f11 = rsc[mf * 2 + 1] * cs1;
            float e0 = ex2f(__int2float_rn(acc[mf][nf][0]) * f00);
            float e1 = ex2f(__int2float_rn(acc[mf][nf][1]) * f01);
            float e2 = ex2f(__int2float_rn(acc[mf][nf][2]) * f10);
            float e3 = ex2f(__int2float_rn(acc[mf][nf][3]) * f11);
            if (diag) {
                e0 = (gcol0     == grow0    ) ? 0.0f : e0;
                e1 = (gcol0 + 1 == grow0    ) ? 0.0f : e1;
                e2 = (gcol0     == grow0 + 8) ? 0.0f : e2;
                e3 = (gcol0 + 1 == grow0 + 8) ? 0.0f : e3;
            }
            rs[mf * 2 + 0] += e0 + e1;
            rs[mf * 2 + 1] += e2 + e3;
            c0 += e0 + e2;
            c1 += e1 + e3;
        }
        if (!diag) {
#pragma unroll
            for (int o = 4; o <= 16; o <<= 1) {
                c0 += __shfl_xor_sync(0xFFFFFFFFu, c0, o);
                c1 += __shfl_xor_sync(0xFFFFFFFFu, c1, o);
            }
            if (lane < 4) {
                atomicAdd(&colsum[coll - (lane & 3) * 2 + lane * 2],     c0);
                atomicAdd(&colsum[coll - (lane & 3) * 2 + lane * 2 + 1], c1);
            }
        }
    }

#pragma unroll
    for (int o = 1; o <= 2; o <<= 1)
#pragma unroll
        for (int j = 0; j < 4; j++)
            rs[j] += __shfl_xor_sync(0xFFFFFFFFu, rs[j], o);
    if ((lane & 3) == 0) {
        int r0 = bi * 128 + warp_m + lrow;
        atomicAdd(&g_rowsum[r0],      rs[0]);
        atomicAdd(&g_rowsum[r0 + 8],  rs[1]);
        atomicAdd(&g_rowsum[r0 + 16], rs[2]);
        atomicAdd(&g_rowsum[r0 + 24], rs[3]);
    }

    if (!diag) {
        __syncthreads();
        if (tid < 128) atomicAdd(&g_rowsum[bj * 128 + tid], colsum[tid]);
    }
#undef ISSUE_CHUNK
}

// ---------------------------------------------------------------------------
// Kernel 3 (parallel): out[0] += block partial of mean log(rowsum/(N-1)+eps)
// ---------------------------------------------------------------------------
__global__ __launch_bounds__(256) void k_reduce(float* __restrict__ out) {
    __shared__ float sh[8];
    int tid = threadIdx.x;
    int i = blockIdx.x * 256 + tid;
    float s = logf(g_rowsum[i] * (1.0f / (float)(NROWS - 1)) + EPS);
#pragma unroll
    for (int o = 16; o; o >>= 1) s += __shfl_xor_sync(0xFFFFFFFFu, s, o);
    if ((tid & 31) == 0) sh[tid >> 5] = s;
    __syncthreads();
    if (tid == 0) {
        float t = 0.0f;
#pragma unroll
        for (int j = 0; j < 8; j++) t += sh[j];
        atomicAdd(out, t * (1.0f / (float)NROWS));
    }
}

// ---------------------------------------------------------------------------
extern "C" void kernel_launch(void* const* d_in, const int* in_sizes, int n_in,
                              void* d_out, int out_size) {
    (void)in_sizes; (void)n_in; (void)out_size;
    const float* x = (const float*)d_in[0];

    cudaFuncSetAttribute(k_gemm, cudaFuncAttributeMaxDynamicSharedMemorySize, SMEM_TOT);

    k_normalize<<<NROWS / 4, 256>>>(x, (float*)d_out);
    k_gemm<<<NTILES, 256, SMEM_TOT>>>();
    k_reduce<<<NROWS / 256, 256>>>((float*)d_out);
}

// round 16
// speedup vs baseline: 2.1316x; 2.1316x over previous
#include <cuda_runtime.h>
#include <cuda_bf16.h>
#include <cstdint>

// ============================================================================
// NegativeContrastiveLoss: x[8192,256] fp32 ->
//   xn = x / max(||x||_2, 1e-12)  (rows)
//   S  = xn @ xn^T / 0.1 ; E = exp(S) with diag zeroed
//   loss = mean_i log( sum_j E_ij / (N-1) + 1e-8 )
//
// R16: revert to the empirically best configuration (R10, 59.7us) after R15
//      falsified int8 IMMA (s8 path is quarter-rate on sm_103: 127us).
//      k_gemm is at the legacy mma.sync issue ceiling (~12.6 cyc/HMMA/SMSP);
//      only residual change: lg2.approx in k_reduce.
//
//      Structure: (1) normalize -> bf16 (2) fused symmetric GEMM
//      (2080 upper-triangular 128x128 tiles, row+col sums, 3-stage cp.async,
//      occupancy 2) (3) parallel log-mean reduce.
// ============================================================================

#define NROWS 8192
#define DIM   256
#define TAU_INV_LOG2E 14.4269504088896340736f   // (1/0.1) * log2(e)
#define EPS   1e-8f
#define LN2   0.69314718055994530942f

__device__ __align__(256) __nv_bfloat16 g_xn[NROWS * DIM];   // 4 MB, L2-resident
__device__ float g_rowsum[NROWS];

static __device__ __forceinline__ unsigned smem_u32(const void* p) {
    unsigned a;
    asm("{ .reg .u64 t; cvta.to.shared.u64 t, %1; cvt.u32.u64 %0, t; }" : "=r"(a) : "l"(p));
    return a;
}
static __device__ __forceinline__ void cp_async16(unsigned saddr, const void* gptr) {
    asm volatile("cp.async.cg.shared.global [%0], [%1], 16;"
                 :: "r"(saddr), "l"(gptr) : "memory");
}
static __device__ __forceinline__ void ldmatrix_x4(unsigned& r0, unsigned& r1,
                                                   unsigned& r2, unsigned& r3,
                                                   unsigned addr) {
    asm volatile("ldmatrix.sync.aligned.m8n8.x4.shared.b16 {%0,%1,%2,%3}, [%4];"
                 : "=r"(r0), "=r"(r1), "=r"(r2), "=r"(r3) : "r"(addr));
}
static __device__ __forceinline__ void mma_16816(float* c, const unsigned* a,
                                                 const unsigned* b) {
    asm volatile(
        "mma.sync.aligned.m16n8k16.row.col.f32.bf16.bf16.f32 "
        "{%0,%1,%2,%3}, {%4,%5,%6,%7}, {%8,%9}, {%0,%1,%2,%3};"
        : "+f"(c[0]), "+f"(c[1]), "+f"(c[2]), "+f"(c[3])
        : "r"(a[0]), "r"(a[1]), "r"(a[2]), "r"(a[3]), "r"(b[0]), "r"(b[1]));
}
static __device__ __forceinline__ float ex2f(float v) {
    float e;
    asm("ex2.approx.f32 %0, %1;" : "=f"(e) : "f"(v));
    return e;
}
static __device__ __forceinline__ float lg2f(float v) {
    float e;
    asm("lg2.approx.f32 %0, %1;" : "=f"(e) : "f"(v));
    return e;
}

// ---------------------------------------------------------------------------
// Kernel 1: row L2-normalize -> bf16; zero rowsum and out[0]. 2 rows/warp.
// ---------------------------------------------------------------------------
__global__ __launch_bounds__(256) void k_normalize(const float* __restrict__ x,
                                                   float* __restrict__ out) {
    int tid = threadIdx.x;
    int gt = blockIdx.x * 256 + tid;
    if (gt < NROWS) g_rowsum[gt] = 0.0f;
    if (gt == 0) out[0] = 0.0f;

    int wg   = blockIdx.x * 8 + (tid >> 5);
    int lane = tid & 31;
    int r0 = wg * 2, r1 = r0 + 1;
    const float4* x0 = reinterpret_cast<const float4*>(x) + (size_t)r0 * (DIM / 4);
    const float4* x1 = reinterpret_cast<const float4*>(x) + (size_t)r1 * (DIM / 4);
    float4 a0 = x0[lane * 2 + 0];
    float4 b0 = x0[lane * 2 + 1];
    float4 a1 = x1[lane * 2 + 0];
    float4 b1 = x1[lane * 2 + 1];

    float s0 = a0.x * a0.x + a0.y * a0.y + a0.z * a0.z + a0.w * a0.w +
               b0.x * b0.x + b0.y * b0.y + b0.z * b0.z + b0.w * b0.w;
    float s1 = a1.x * a1.x + a1.y * a1.y + a1.z * a1.z + a1.w * a1.w +
               b1.x * b1.x + b1.y * b1.y + b1.z * b1.z + b1.w * b1.w;
#pragma unroll
    for (int o = 16; o; o >>= 1) {
        s0 += __shfl_xor_sync(0xFFFFFFFFu, s0, o);
        s1 += __shfl_xor_sync(0xFFFFFFFFu, s1, o);
    }
    float sc0 = 1.0f / fmaxf(sqrtf(s0), 1e-12f);
    float sc1 = 1.0f / fmaxf(sqrtf(s1), 1e-12f);

    __nv_bfloat162 q0 = __floats2bfloat162_rn(a0.x * sc0, a0.y * sc0);
    __nv_bfloat162 q1 = __floats2bfloat162_rn(a0.z * sc0, a0.w * sc0);
    __nv_bfloat162 q2 = __floats2bfloat162_rn(b0.x * sc0, b0.y * sc0);
    __nv_bfloat162 q3 = __floats2bfloat162_rn(b0.z * sc0, b0.w * sc0);
    uint4 o0;
    o0.x = *reinterpret_cast<unsigned*>(&q0);
    o0.y = *reinterpret_cast<unsigned*>(&q1);
    o0.z = *reinterpret_cast<unsigned*>(&q2);
    o0.w = *reinterpret_cast<unsigned*>(&q3);
    reinterpret_cast<uint4*>(g_xn)[r0 * (DIM / 8) + lane] = o0;

    __nv_bfloat162 u0 = __floats2bfloat162_rn(a1.x * sc1, a1.y * sc1);
    __nv_bfloat162 u1 = __floats2bfloat162_rn(a1.z * sc1, a1.w * sc1);
    __nv_bfloat162 u2 = __floats2bfloat162_rn(b1.x * sc1, b1.y * sc1);
    __nv_bfloat162 u3 = __floats2bfloat162_rn(b1.z * sc1, b1.w * sc1);
    uint4 o1;
    o1.x = *reinterpret_cast<unsigned*>(&u0);
    o1.y = *reinterpret_cast<unsigned*>(&u1);
    o1.z = *reinterpret_cast<unsigned*>(&u2);
    o1.w = *reinterpret_cast<unsigned*>(&u3);
    reinterpret_cast<uint4*>(g_xn)[r1 * (DIM / 8) + lane] = o1;
}

// ---------------------------------------------------------------------------
// Kernel 2: fused GEMM + exp + row/col sums, upper-triangular tiles only.
// CTA tile 128x128, K=256 in 4 chunks of 64, 3-stage cp.async pipeline
// (96 KB smem, one __syncthreads per chunk, issue-before-compute).
// 8 warps as 4(M) x 2(N), warp tile 32x64, f32 accumulators.
// ---------------------------------------------------------------------------
#define STAGE_BYTES 32768
#define SMEM_TOT    98304
#define NB 64
#define NTILES (NB * (NB + 1) / 2)  // 2080
#define NKC 4

__global__ __launch_bounds__(256, 2) void k_gemm() {
    extern __shared__ char smem[];
    unsigned sb = smem_u32(smem);
    int tid  = threadIdx.x;
    int wid  = tid >> 5, lane = tid & 31;

    // triangular decode: k -> (bi, bj), bi <= bj
    int k = blockIdx.x;
    int bi = (int)floorf((float)NB + 0.5f -
                         sqrtf(((float)NB + 0.5f) * ((float)NB + 0.5f) - 2.0f * (float)k));
    while (NB * (bi + 1) - ((bi + 1) * bi) / 2 <= k) bi++;
    while (NB * bi - (bi * (bi - 1)) / 2 > k) bi--;
    int bj = bi + (k - (NB * bi - (bi * (bi - 1)) / 2));
    bool diag = (bi == bj);

    int warp_m = (wid & 3) * 32;
    int warp_n = (wid >> 2) * 64;

    int lr = tid >> 3;
    int lc = tid & 7;
    unsigned ssw = (unsigned)((lc ^ (lr & 7)) << 4);
    const char* gA = reinterpret_cast<const char*>(g_xn) + (size_t)(bi * 128 + lr) * 512 + lc * 16;
    const char* gB = reinterpret_cast<const char*>(g_xn) + (size_t)(bj * 128 + lr) * 512 + lc * 16;

#define ISSUE_STAGE(kc, buf)                                                     \
    do {                                                                         \
        unsigned ab_ = sb + (buf) * STAGE_BYTES;                                 \
        unsigned bb_ = ab_ + 16384;                                              \
        _Pragma("unroll")                                                        \
        for (int it = 0; it < 4; it++)                                           \
            cp_async16(ab_ + (unsigned)(lr + it * 32) * 128 + ssw,               \
                       gA + (size_t)it * 32 * 512 + (kc) * 128);                 \
        _Pragma("unroll")                                                        \
        for (int it = 0; it < 4; it++)                                           \
            cp_async16(bb_ + (unsigned)(lr + it * 32) * 128 + ssw,               \
                       gB + (size_t)it * 32 * 512 + (kc) * 128);                 \
        asm volatile("cp.async.commit_group;" ::: "memory");                     \
    } while (0)

    float acc[2][8][4];
#pragma unroll
    for (int mf = 0; mf < 2; mf++)
#pragma unroll
        for (int nf = 0; nf < 8; nf++)
#pragma unroll
            for (int j = 0; j < 4; j++) acc[mf][nf][j] = 0.0f;

    ISSUE_STAGE(0, 0);
    ISSUE_STAGE(1, 1);

#pragma unroll
    for (int kc = 0; kc < NKC; kc++) {
        if (kc < NKC - 1) asm volatile("cp.async.wait_group 1;" ::: "memory");
        else              asm volatile("cp.async.wait_group 0;" ::: "memory");
        __syncthreads();   // chunk kc visible; all warps past iter kc-1

        if (kc + 2 < NKC) ISSUE_STAGE(kc + 2, (kc + 2) % 3);

        unsigned ab = sb + (kc % 3) * STAGE_BYTES;
        unsigned bb = ab + 16384;

#pragma unroll
        for (int ks = 0; ks < 4; ks++) {
            unsigned a[2][4];
#pragma unroll
            for (int mf = 0; mf < 2; mf++) {
                int r = warp_m + mf * 16 + (lane & 15);
                int ch = ks * 2 + (lane >> 4);
                ldmatrix_x4(a[mf][0], a[mf][1], a[mf][2], a[mf][3],
                            ab + r * 128 + ((ch ^ (r & 7)) << 4));
            }
            unsigned b[8][2];
#pragma unroll
            for (int p = 0; p < 4; p++) {
                int g = lane >> 3;
                int r = warp_n + p * 16 + (g >> 1) * 8 + (lane & 7);
                int ch = ks * 2 + (g & 1);
                unsigned r0, r1, r2, r3;
                ldmatrix_x4(r0, r1, r2, r3, bb + r * 128 + ((ch ^ (r & 7)) << 4));
                b[p * 2 + 0][0] = r0; b[p * 2 + 0][1] = r1;
                b[p * 2 + 1][0] = r2; b[p * 2 + 1][1] = r3;
            }
#pragma unroll
            for (int mf = 0; mf < 2; mf++)
#pragma unroll
                for (int nf = 0; nf < 8; nf++)
                    mma_16816(acc[mf][nf], a[mf], b[nf]);
        }
    }

    // ---- epilogue: exp, diag zero, row sums + (off-diag) column sums ----
    __syncthreads();
    float* colsum = reinterpret_cast<float*>(smem);
    if (!diag) {
        if (tid < 128) colsum[tid] = 0.0f;
        __syncthreads();
    }

    float rs[4] = {0.0f, 0.0f, 0.0f, 0.0f};
    int lrow = lane >> 2;
#pragma unroll
    for (int nf = 0; nf < 8; nf++) {
        float c0 = 0.0f, c1 = 0.0f;
        int gcol0 = bj * 128 + warp_n + nf * 8 + (lane & 3) * 2;
#pragma unroll
        for (int mf = 0; mf < 2; mf++) {
            int grow0 = bi * 128 + warp_m + mf * 16 + lrow;
            float e0 = ex2f(acc[mf][nf][0] * TAU_INV_LOG2E);
            float e1 = ex2f(acc[mf][nf][1] * TAU_INV_LOG2E);
            float e2 = ex2f(acc[mf][nf][2] * TAU_INV_LOG2E);
            float e3 = ex2f(acc[mf][nf][3] * TAU_INV_LOG2E);
            if (diag) {
                e0 = (gcol0     == grow0    ) ? 0.0f : e0;
                e1 = (gcol0 + 1 == grow0    ) ? 0.0f : e1;
                e2 = (gcol0     == grow0 + 8) ? 0.0f : e2;
                e3 = (gcol0 + 1 == grow0 + 8) ? 0.0f : e3;
            }
            rs[mf * 2 + 0] += e0 + e1;
            rs[mf * 2 + 1] += e2 + e3;
            c0 += e0 + e2;
            c1 += e1 + e3;
        }
        if (!diag) {
#pragma unroll
            for (int o = 4; o <= 16; o <<= 1) {
                c0 += __shfl_xor_sync(0xFFFFFFFFu, c0, o);
                c1 += __shfl_xor_sync(0xFFFFFFFFu, c1, o);
            }
            if (lane < 4) {
                int cc = warp_n + nf * 8 + lane * 2;
                atomicAdd(&colsum[cc],     c0);
                atomicAdd(&colsum[cc + 1], c1);
            }
        }
    }

#pragma unroll
    for (int o = 1; o <= 2; o <<= 1)
#pragma unroll
        for (int j = 0; j < 4; j++)
            rs[j] += __shfl_xor_sync(0xFFFFFFFFu, rs[j], o);
    if ((lane & 3) == 0) {
        int r0 = bi * 128 + warp_m + lrow;
        atomicAdd(&g_rowsum[r0],      rs[0]);
        atomicAdd(&g_rowsum[r0 + 8],  rs[1]);
        atomicAdd(&g_rowsum[r0 + 16], rs[2]);
        atomicAdd(&g_rowsum[r0 + 24], rs[3]);
    }

    if (!diag) {
        __syncthreads();
        if (tid < 128) atomicAdd(&g_rowsum[bj * 128 + tid], colsum[tid]);
    }
#undef ISSUE_STAGE
}

// ---------------------------------------------------------------------------
// Kernel 3 (parallel): out[0] += block partial of mean log(rowsum/(N-1)+eps)
// log via MUFU lg2 (ln x = lg2(x) * ln2); ~22.5-bit accuracy, ample here.
// ---------------------------------------------------------------------------
__global__ __launch_bounds__(256) void k_reduce(float* __restrict__ out) {
    __shared__ float sh[8];
    int tid = threadIdx.x;
    int i = blockIdx.x * 256 + tid;
    float s = lg2f(g_rowsum[i] * (1.0f / (float)(NROWS - 1)) + EPS);
#pragma unroll
    for (int o = 16; o; o >>= 1) s += __shfl_xor_sync(0xFFFFFFFFu, s, o);
    if ((tid & 31) == 0) sh[tid >> 5] = s;
    __syncthreads();
    if (tid == 0) {
        float t = 0.0f;
#pragma unroll
        for (int j = 0; j < 8; j++) t += sh[j];
        atomicAdd(out, t * (LN2 / (float)NROWS));
    }
}

// ---------------------------------------------------------------------------
extern "C" void kernel_launch(void* const* d_in, const int* in_sizes, int n_in,
                              void* d_out, int out_size) {
    (void)in_sizes; (void)n_in; (void)out_size;
    const float* x = (const float*)d_in[0];

    cudaFuncSetAttribute(k_gemm, cudaFuncAttributeMaxDynamicSharedMemorySize, SMEM_TOT);

    k_normalize<<<NROWS / 16, 256>>>(x, (float*)d_out);
    k_gemm<<<NTILES, 256, SMEM_TOT>>>();
    k_reduce<<<NROWS / 256, 256>>>((float*)d_out);
}

// round 17
// speedup vs baseline: 2.1362x; 1.0021x over previous
#include <cuda_runtime.h>
#include <cuda_bf16.h>
#include <cstdint>

// ============================================================================
// NegativeContrastiveLoss: x[8192,256] fp32 ->
//   xn = x / max(||x||_2, 1e-12)  (rows)
//   S  = xn @ xn^T / 0.1 ; E = exp(S) with diag zeroed
//   loss = mean_i log( sum_j E_ij / (N-1) + 1e-8 )
//
// R17: fix the tail wave. 2080 tiles on 296 CTA slots = 7.03 -> an 8th wave
//      of just 8 CTAs (~6 us of near-idle chip). Split the last 8 tiles into
//      32 quarter-tiles (128x32, N-split is free since row/col sums are
//      additive): 2072 full CTAs = exactly 7 waves, + a short quarter-length
//      tail wave. Makespan 8.0 -> 7.25 tile units.
//      Hot path (templated NPAIR=4) is identical to R16's mainloop.
// ============================================================================

#define NROWS 8192
#define DIM   256
#define TAU_INV_LOG2E 14.4269504088896340736f   // (1/0.1) * log2(e)
#define EPS   1e-8f
#define LN2   0.69314718055994530942f

__device__ __align__(256) __nv_bfloat16 g_xn[NROWS * DIM];   // 4 MB, L2-resident
__device__ float g_rowsum[NROWS];

static __device__ __forceinline__ unsigned smem_u32(const void* p) {
    unsigned a;
    asm("{ .reg .u64 t; cvta.to.shared.u64 t, %1; cvt.u32.u64 %0, t; }" : "=r"(a) : "l"(p));
    return a;
}
static __device__ __forceinline__ void cp_async16(unsigned saddr, const void* gptr) {
    asm volatile("cp.async.cg.shared.global [%0], [%1], 16;"
                 :: "r"(saddr), "l"(gptr) : "memory");
}
static __device__ __forceinline__ void ldmatrix_x4(unsigned& r0, unsigned& r1,
                                                   unsigned& r2, unsigned& r3,
                                                   unsigned addr) {
    asm volatile("ldmatrix.sync.aligned.m8n8.x4.shared.b16 {%0,%1,%2,%3}, [%4];"
                 : "=r"(r0), "=r"(r1), "=r"(r2), "=r"(r3) : "r"(addr));
}
static __device__ __forceinline__ void mma_16816(float* c, const unsigned* a,
                                                 const unsigned* b) {
    asm volatile(
        "mma.sync.aligned.m16n8k16.row.col.f32.bf16.bf16.f32 "
        "{%0,%1,%2,%3}, {%4,%5,%6,%7}, {%8,%9}, {%0,%1,%2,%3};"
        : "+f"(c[0]), "+f"(c[1]), "+f"(c[2]), "+f"(c[3])
        : "r"(a[0]), "r"(a[1]), "r"(a[2]), "r"(a[3]), "r"(b[0]), "r"(b[1]));
}
static __device__ __forceinline__ float ex2f(float v) {
    float e;
    asm("ex2.approx.f32 %0, %1;" : "=f"(e) : "f"(v));
    return e;
}
static __device__ __forceinline__ float lg2f(float v) {
    float e;
    asm("lg2.approx.f32 %0, %1;" : "=f"(e) : "f"(v));
    return e;
}

// ---------------------------------------------------------------------------
// Kernel 1: row L2-normalize -> bf16; zero rowsum and out[0]. 2 rows/warp.
// ---------------------------------------------------------------------------
__global__ __launch_bounds__(256) void k_normalize(const float* __restrict__ x,
                                                   float* __restrict__ out) {
    int tid = threadIdx.x;
    int gt = blockIdx.x * 256 + tid;
    if (gt < NROWS) g_rowsum[gt] = 0.0f;
    if (gt == 0) out[0] = 0.0f;

    int wg   = blockIdx.x * 8 + (tid >> 5);
    int lane = tid & 31;
    int r0 = wg * 2, r1 = r0 + 1;
    const float4* x0 = reinterpret_cast<const float4*>(x) + (size_t)r0 * (DIM / 4);
    const float4* x1 = reinterpret_cast<const float4*>(x) + (size_t)r1 * (DIM / 4);
    float4 a0 = x0[lane * 2 + 0];
    float4 b0 = x0[lane * 2 + 1];
    float4 a1 = x1[lane * 2 + 0];
    float4 b1 = x1[lane * 2 + 1];

    float s0 = a0.x * a0.x + a0.y * a0.y + a0.z * a0.z + a0.w * a0.w +
               b0.x * b0.x + b0.y * b0.y + b0.z * b0.z + b0.w * b0.w;
    float s1 = a1.x * a1.x + a1.y * a1.y + a1.z * a1.z + a1.w * a1.w +
               b1.x * b1.x + b1.y * b1.y + b1.z * b1.z + b1.w * b1.w;
#pragma unroll
    for (int o = 16; o; o >>= 1) {
        s0 += __shfl_xor_sync(0xFFFFFFFFu, s0, o);
        s1 += __shfl_xor_sync(0xFFFFFFFFu, s1, o);
    }
    float sc0 = 1.0f / fmaxf(sqrtf(s0), 1e-12f);
    float sc1 = 1.0f / fmaxf(sqrtf(s1), 1e-12f);

    __nv_bfloat162 q0 = __floats2bfloat162_rn(a0.x * sc0, a0.y * sc0);
    __nv_bfloat162 q1 = __floats2bfloat162_rn(a0.z * sc0, a0.w * sc0);
    __nv_bfloat162 q2 = __floats2bfloat162_rn(b0.x * sc0, b0.y * sc0);
    __nv_bfloat162 q3 = __floats2bfloat162_rn(b0.z * sc0, b0.w * sc0);
    uint4 o0;
    o0.x = *reinterpret_cast<unsigned*>(&q0);
    o0.y = *reinterpret_cast<unsigned*>(&q1);
    o0.z = *reinterpret_cast<unsigned*>(&q2);
    o0.w = *reinterpret_cast<unsigned*>(&q3);
    reinterpret_cast<uint4*>(g_xn)[r0 * (DIM / 8) + lane] = o0;

    __nv_bfloat162 u0 = __floats2bfloat162_rn(a1.x * sc1, a1.y * sc1);
    __nv_bfloat162 u1 = __floats2bfloat162_rn(a1.z * sc1, a1.w * sc1);
    __nv_bfloat162 u2 = __floats2bfloat162_rn(b1.x * sc1, b1.y * sc1);
    __nv_bfloat162 u3 = __floats2bfloat162_rn(b1.z * sc1, b1.w * sc1);
    uint4 o1;
    o1.x = *reinterpret_cast<unsigned*>(&u0);
    o1.y = *reinterpret_cast<unsigned*>(&u1);
    o1.z = *reinterpret_cast<unsigned*>(&u2);
    o1.w = *reinterpret_cast<unsigned*>(&u3);
    reinterpret_cast<uint4*>(g_xn)[r1 * (DIM / 8) + lane] = o1;
}

// ---------------------------------------------------------------------------
// Kernel 2: fused GEMM + exp + row/col sums, upper-triangular tiles only.
//
// Tile body templated on NPAIR (B ldmatrix groups per k-step):
//   NPAIR=4 -> 128x128 tile (8 warps as 4Mx2N, warp 32x64)  [2072 CTAs]
//   NPAIR=1 -> 128x32 quarter tile (warp 32x16)              [32 CTAs, tail]
// K=256 in 4 chunks of 64, 3-stage cp.async pipeline (96 KB smem,
// one __syncthreads per chunk, issue-before-compute).
// coff = column offset of this tile within block bj's 128 columns.
// ---------------------------------------------------------------------------
#define STAGE_BYTES 32768
#define SMEM_TOT    98304
#define NB 64
#define NTILES (NB * (NB + 1) / 2)  // 2080
#define FULL_CTAS 2072               // 296 slots * 7 waves
#define NKC 4

template <int NPAIR>
static __device__ __forceinline__ void gemm_tile(char* smem, unsigned sb,
                                                 int tid, int wid, int lane,
                                                 int bi, int bj, int coff,
                                                 bool diag) {
    const int NFr = NPAIR * 2;           // n8 fragments per warp
    int warp_m = (wid & 3) * 32;
    int warp_n = (wid >> 2) * (NPAIR * 16);

    int lr = tid >> 3;
    int lc = tid & 7;
    unsigned ssw = (unsigned)((lc ^ (lr & 7)) << 4);
    const char* gA = reinterpret_cast<const char*>(g_xn) + (size_t)(bi * 128 + lr) * 512 + lc * 16;
    const char* gB = reinterpret_cast<const char*>(g_xn) + (size_t)(bj * 128 + coff + lr) * 512 + lc * 16;

#define ISSUE_STAGE(kc, buf)                                                     \
    do {                                                                         \
        unsigned ab_ = sb + (buf) * STAGE_BYTES;                                 \
        unsigned bb_ = ab_ + 16384;                                              \
        _Pragma("unroll")                                                        \
        for (int it = 0; it < 4; it++)                                           \
            cp_async16(ab_ + (unsigned)(lr + it * 32) * 128 + ssw,               \
                       gA + (size_t)it * 32 * 512 + (kc) * 128);                 \
        _Pragma("unroll")                                                        \
        for (int it = 0; it < NPAIR; it++)                                       \
            cp_async16(bb_ + (unsigned)(lr + it * 32) * 128 + ssw,               \
                       gB + (size_t)it * 32 * 512 + (kc) * 128);                 \
        asm volatile("cp.async.commit_group;" ::: "memory");                     \
    } while (0)

    float acc[2][NFr][4];
#pragma unroll
    for (int mf = 0; mf < 2; mf++)
#pragma unroll
        for (int nf = 0; nf < NFr; nf++)
#pragma unroll
            for (int j = 0; j < 4; j++) acc[mf][nf][j] = 0.0f;

    ISSUE_STAGE(0, 0);
    ISSUE_STAGE(1, 1);

#pragma unroll
    for (int kc = 0; kc < NKC; kc++) {
        if (kc < NKC - 1) asm volatile("cp.async.wait_group 1;" ::: "memory");
        else              asm volatile("cp.async.wait_group 0;" ::: "memory");
        __syncthreads();

        if (kc + 2 < NKC) ISSUE_STAGE(kc + 2, (kc + 2) % 3);

        unsigned ab = sb + (kc % 3) * STAGE_BYTES;
        unsigned bb = ab + 16384;

#pragma unroll
        for (int ks = 0; ks < 4; ks++) {
            unsigned a[2][4];
#pragma unroll
            for (int mf = 0; mf < 2; mf++) {
                int r = warp_m + mf * 16 + (lane & 15);
                int ch = ks * 2 + (lane >> 4);
                ldmatrix_x4(a[mf][0], a[mf][1], a[mf][2], a[mf][3],
                            ab + r * 128 + ((ch ^ (r & 7)) << 4));
            }
            unsigned b[NFr][2];
#pragma unroll
            for (int p = 0; p < NPAIR; p++) {
                int g = lane >> 3;
                int r = warp_n + p * 16 + (g >> 1) * 8 + (lane & 7);
                int ch = ks * 2 + (g & 1);
                unsigned r0, r1, r2, r3;
                ldmatrix_x4(r0, r1, r2, r3, bb + r * 128 + ((ch ^ (r & 7)) << 4));
                b[p * 2 + 0][0] = r0; b[p * 2 + 0][1] = r1;
                b[p * 2 + 1][0] = r2; b[p * 2 + 1][1] = r3;
            }
#pragma unroll
            for (int mf = 0; mf < 2; mf++)
#pragma unroll
                for (int nf = 0; nf < NFr; nf++)
                    mma_16816(acc[mf][nf], a[mf], b[nf]);
        }
    }
#undef ISSUE_STAGE

    // ---- epilogue: exp, diag zero, row sums + (off-diag) column sums ----
    __syncthreads();
    float* colsum = reinterpret_cast<float*>(smem);
    if (!diag) {
        if (tid < NPAIR * 32) colsum[tid] = 0.0f;
        __syncthreads();
    }

    float rs[4] = {0.0f, 0.0f, 0.0f, 0.0f};
    int lrow = lane >> 2;
#pragma unroll
    for (int nf = 0; nf < NFr; nf++) {
        float c0 = 0.0f, c1 = 0.0f;
        int lcol0 = warp_n + nf * 8 + (lane & 3) * 2;     // local col in tile
        int gcol0 = bj * 128 + coff + lcol0;
#pragma unroll
        for (int mf = 0; mf < 2; mf++) {
            int grow0 = bi * 128 + warp_m + mf * 16 + lrow;
            float e0 = ex2f(acc[mf][nf][0] * TAU_INV_LOG2E);
            float e1 = ex2f(acc[mf][nf][1] * TAU_INV_LOG2E);
            float e2 = ex2f(acc[mf][nf][2] * TAU_INV_LOG2E);
            float e3 = ex2f(acc[mf][nf][3] * TAU_INV_LOG2E);
            if (diag) {
                e0 = (gcol0     == grow0    ) ? 0.0f : e0;
                e1 = (gcol0 + 1 == grow0    ) ? 0.0f : e1;
                e2 = (gcol0     == grow0 + 8) ? 0.0f : e2;
                e3 = (gcol0 + 1 == grow0 + 8) ? 0.0f : e3;
            }
            rs[mf * 2 + 0] += e0 + e1;
            rs[mf * 2 + 1] += e2 + e3;
            c0 += e0 + e2;
            c1 += e1 + e3;
        }
        if (!diag) {
#pragma unroll
            for (int o = 4; o <= 16; o <<= 1) {
                c0 += __shfl_xor_sync(0xFFFFFFFFu, c0, o);
                c1 += __shfl_xor_sync(0xFFFFFFFFu, c1, o);
            }
            if (lane < 4) {
                int cc = warp_n + nf * 8 + lane * 2;
                atomicAdd(&colsum[cc],     c0);
                atomicAdd(&colsum[cc + 1], c1);
            }
        }
    }

#pragma unroll
    for (int o = 1; o <= 2; o <<= 1)
#pragma unroll
        for (int j = 0; j < 4; j++)
            rs[j] += __shfl_xor_sync(0xFFFFFFFFu, rs[j], o);
    if ((lane & 3) == 0) {
        int r0 = bi * 128 + warp_m + lrow;
        atomicAdd(&g_rowsum[r0],      rs[0]);
        atomicAdd(&g_rowsum[r0 + 8],  rs[1]);
        atomicAdd(&g_rowsum[r0 + 16], rs[2]);
        atomicAdd(&g_rowsum[r0 + 24], rs[3]);
    }

    if (!diag) {
        __syncthreads();
        if (tid < NPAIR * 32)
            atomicAdd(&g_rowsum[bj * 128 + coff + tid], colsum[tid]);
    }
}

__global__ __launch_bounds__(256, 2) void k_gemm() {
    extern __shared__ char smem[];
    unsigned sb = smem_u32(smem);
    int tid = threadIdx.x;
    int wid = tid >> 5, lane = tid & 31;

    int bid = blockIdx.x;
    int k, coff;
    bool full = (bid < FULL_CTAS);
    if (full) { k = bid; coff = 0; }
    else      { int q = bid - FULL_CTAS; k = FULL_CTAS + (q >> 2); coff = (q & 3) * 32; }

    // triangular decode: k -> (bi, bj), bi <= bj
    int bi = (int)floorf((float)NB + 0.5f -
                         sqrtf(((float)NB + 0.5f) * ((float)NB + 0.5f) - 2.0f * (float)k));
    while (NB * (bi + 1) - ((bi + 1) * bi) / 2 <= k) bi++;
    while (NB * bi - (bi * (bi - 1)) / 2 > k) bi--;
    int bj = bi + (k - (NB * bi - (bi * (bi - 1)) / 2));
    bool diag = (bi == bj);

    if (full) gemm_tile<4>(smem, sb, tid, wid, lane, bi, bj, coff, diag);
    else      gemm_tile<1>(smem, sb, tid, wid, lane, bi, bj, coff, diag);
}

// ---------------------------------------------------------------------------
// Kernel 3 (parallel): out[0] += block partial of mean log(rowsum/(N-1)+eps)
// ---------------------------------------------------------------------------
__global__ __launch_bounds__(256) void k_reduce(float* __restrict__ out) {
    __shared__ float sh[8];
    int tid = threadIdx.x;
    int i = blockIdx.x * 256 + tid;
    float s = lg2f(g_rowsum[i] * (1.0f / (float)(NROWS - 1)) + EPS);
#pragma unroll
    for (int o = 16; o; o >>= 1) s += __shfl_xor_sync(0xFFFFFFFFu, s, o);
    if ((tid & 31) == 0) sh[tid >> 5] = s;
    __syncthreads();
    if (tid == 0) {
        float t = 0.0f;
#pragma unroll
        for (int j = 0; j < 8; j++) t += sh[j];
        atomicAdd(out, t * (LN2 / (float)NROWS));
    }
}

// ---------------------------------------------------------------------------
extern "C" void kernel_launch(void* const* d_in, const int* in_sizes, int n_in,
                              void* d_out, int out_size) {
    (void)in_sizes; (void)n_in; (void)out_size;
    const float* x = (const float*)d_in[0];

    cudaFuncSetAttribute(k_gemm, cudaFuncAttributeMaxDynamicSharedMemorySize, SMEM_TOT);

    k_normalize<<<NROWS / 16, 256>>>(x, (float*)d_out);
    k_gemm<<<FULL_CTAS + 32, 256, SMEM_TOT>>>();
    k_reduce<<<NROWS / 256, 256>>>((float*)d_out);
}